// round 7
// baseline (speedup 1.0000x reference)
#include <cuda_runtime.h>
#include <cuda_bf16.h>
#include <cstdint>

#define BB 32
#define NN 512
#define DINN 768
#define DOUTT 256
#define NEGV -9.0e15f
#define SLOPE 0.2f

// ---------------------------------------------------------------------------
// Scratch (allocation-free). Referenced ONLY in device code.
// ---------------------------------------------------------------------------
__device__ __nv_bfloat16 g_h_hi[(long)BB * NN * DINN];          // h hi/lo [b][n][din]
__device__ __nv_bfloat16 g_h_lo[(long)BB * NN * DINN];
__device__ __nv_bfloat16 g_WT_hi[DOUTT * DINN];                 // W^T  [dout][din]
__device__ __nv_bfloat16 g_WT_lo[DOUTT * DINN];
__device__ __nv_bfloat16 g_WhT_hi[(long)BB * DOUTT * NN];       // Wh^T [b][dout][node]
__device__ __nv_bfloat16 g_WhT_lo[(long)BB * DOUTT * NN];
__device__ __nv_bfloat16 g_att_hi[(long)BB * NN * NN];          // att  [b][i][j]
__device__ __nv_bfloat16 g_att_lo[(long)BB * NN * NN];
__device__ float g_s1[BB * NN];
__device__ float g_s2[BB * NN];

// ---------------------------------------------------------------------------
__device__ __forceinline__ uint32_t smem_u32(const void* p) {
    uint32_t a;
    asm("{ .reg .u64 t; cvta.to.shared.u64 t, %1; cvt.u32.u64 %0, t; }" : "=r"(a) : "l"(p));
    return a;
}
__device__ __forceinline__ uint32_t pk2(float a, float b) {
    return (uint32_t)__bfloat16_as_ushort(__float2bfloat16(a)) |
           ((uint32_t)__bfloat16_as_ushort(__float2bfloat16(b)) << 16);
}
__device__ __forceinline__ float bhi(float v) {
    return __bfloat162float(__float2bfloat16(v));
}
__device__ __forceinline__ void cpa16(uint32_t s, const void* g) {
    asm volatile("cp.async.cg.shared.global [%0], [%1], 16;" :: "r"(s), "l"(g));
}

#define LDSM_X4(R, A)                                                         \
    asm volatile("ldmatrix.sync.aligned.m8n8.x4.shared.b16 {%0,%1,%2,%3}, [%4];" \
        : "=r"((R)[0]), "=r"((R)[1]), "=r"((R)[2]), "=r"((R)[3]) : "r"(A))

#define MMA16816(D, A, B0, B1)                                                \
    asm volatile("mma.sync.aligned.m16n8k16.row.col.f32.bf16.bf16.f32 "       \
        "{%0,%1,%2,%3},{%4,%5,%6,%7},{%8,%9},{%0,%1,%2,%3};"                  \
        : "+f"((D)[0]), "+f"((D)[1]), "+f"((D)[2]), "+f"((D)[3])              \
        : "r"((A)[0]), "r"((A)[1]), "r"((A)[2]), "r"((A)[3]), "r"(B0), "r"(B1))

// per-stage operand smem: A_hi | A_lo | B_hi | B_lo ; rows stride 80 B
#define AHI 0
#define ALO 10240
#define BHI 20480
#define BLO 40960
#define BUFB 61440
#define NSTAGE 3
#define STG1 132      // GEMM1 stage: st[col*132 + row], 256x132 fp32
#define STG2 264      // GEMM2 stage: st[row*264 + col], 128x264 fp32
#define SMEM_TOTAL (NSTAGE * BUFB + 512)   // 184832

// ---------------------------------------------------------------------------
// Pre-pass: W [din][dout] fp32 -> W^T hi/lo bf16 [dout][din]
// ---------------------------------------------------------------------------
__global__ __launch_bounds__(256)
void k_transW(const float* __restrict__ W)
{
    __shared__ float t[32][33];
    const int k0 = blockIdx.x * 32, n0 = blockIdx.y * 32;
    const int tx = threadIdx.x & 31, ty = threadIdx.x >> 5;
    #pragma unroll
    for (int j = 0; j < 4; j++) {
        int r = ty + j * 8;
        t[r][tx] = W[(long)(k0 + r) * DOUTT + n0 + tx];
    }
    __syncthreads();
    #pragma unroll
    for (int j = 0; j < 4; j++) {
        int r = ty + j * 8;
        float v = t[tx][r];
        __nv_bfloat16 h = __float2bfloat16(v);
        long o = (long)(n0 + r) * DINN + k0 + tx;
        g_WT_hi[o] = h;
        g_WT_lo[o] = __float2bfloat16(v - __bfloat162float(h));
    }
}

// ---------------------------------------------------------------------------
// Pre-pass: h fp32 -> hi/lo bf16 (same layout)
// ---------------------------------------------------------------------------
__global__ __launch_bounds__(512)
void k_splitH(const float* __restrict__ h)
{
    const long total4 = (long)BB * NN * DINN / 4;
    for (long i = (long)blockIdx.x * 512 + threadIdx.x; i < total4;
         i += (long)gridDim.x * 512) {
        float4 v = __ldg((const float4*)h + i);
        *(uint2*)(g_h_hi + i * 4) = make_uint2(pk2(v.x, v.y), pk2(v.z, v.w));
        *(uint2*)(g_h_lo + i * 4) =
            make_uint2(pk2(v.x - bhi(v.x), v.y - bhi(v.y)),
                       pk2(v.z - bhi(v.z), v.w - bhi(v.w)));
    }
}

// ---------------------------------------------------------------------------
// Warp-MMA GEMM: D[128 x 256] = A[128xK] * B^T[256xK], bf16 hi/lo 3-product.
// IS1: A = h hi/lo, B = W^T; epi -> WhT hi/lo + s1/s2 (fused)
// !IS1: A = att hi/lo, B = Wh^T; epi -> hp fp32
// grid (NN/128=4, BB); 512 threads; warps 2(M)x8(N), 64x32 per warp; 3-stage.
// ---------------------------------------------------------------------------
template<int KDIM, bool IS1>
__global__ __launch_bounds__(512, 1)
void mma_gemm(const int* __restrict__ pos, const float* __restrict__ pt,
              const float* __restrict__ a1v, const float* __restrict__ a2v,
              float* __restrict__ hp)
{
    extern __shared__ char smem[];
    const uint32_t sbase = smem_u32(smem);
    const int tid = threadIdx.x;
    const int lane = tid & 31, wid = tid >> 5;
    const int wm = wid & 1, wn = wid >> 1;
    const int b = blockIdx.y;
    const int rowBase = blockIdx.x * 128;

    const __nv_bfloat16* Agh = IS1 ? g_h_hi : g_att_hi;
    const __nv_bfloat16* Agl = IS1 ? g_h_lo : g_att_lo;
    const __nv_bfloat16* Bgh = IS1 ? g_WT_hi : g_WhT_hi;
    const __nv_bfloat16* Bgl = IS1 ? g_WT_lo : g_WhT_lo;
    const int AK = IS1 ? DINN : NN;

    float acc[4][4][4];
    #pragma unroll
    for (int i = 0; i < 4; i++)
        #pragma unroll
        for (int j = 0; j < 4; j++)
            #pragma unroll
            for (int r = 0; r < 4; r++) acc[i][j][r] = 0.f;

    auto ISSUE = [&](int kc, int s) {
        const uint32_t sb2 = sbase + s * BUFB;
        {   // A: 128 rows x 64 B, hi+lo
            int r = tid >> 2, c4 = tid & 3;
            long go = ((long)b * NN + rowBase + r) * (long)AK + kc + c4 * 8;
            uint32_t so = r * 80 + c4 * 16;
            cpa16(sb2 + AHI + so, Agh + go);
            cpa16(sb2 + ALO + so, Agl + go);
        }
        #pragma unroll
        for (int i = 0; i < 2; i++) {   // B: 256 rows x 64 B, hi+lo
            int idx = i * 512 + tid;
            int r = idx >> 2, c4 = idx & 3;
            long go = IS1 ? ((long)r * DINN + kc + c4 * 8)
                          : (((long)b * DOUTT + r) * NN + kc + c4 * 8);
            uint32_t so = r * 80 + c4 * 16;
            cpa16(sb2 + BHI + so, Bgh + go);
            cpa16(sb2 + BLO + so, Bgl + go);
        }
        asm volatile("cp.async.commit_group;" ::: "memory");
    };

    const int arow = (wm * 64 + ((lane >> 3) & 1) * 8 + (lane & 7)) * 80;
    const int brow = (wn * 32 + ((lane >> 3) & 1) * 8 + (lane & 7)) * 80;

    auto COMPUTE = [&](int s) {
        const uint32_t base = sbase + s * BUFB;
        #pragma unroll
        for (int k16 = 0; k16 < 2; k16++) {
            const int kb = (k16 * 16 + (lane >> 4) * 8) * 2;
            uint32_t a_hi[4][4], a_lo[4][4];
            #pragma unroll
            for (int am = 0; am < 4; am++) {
                LDSM_X4(a_hi[am], base + AHI + arow + am * 16 * 80 + kb);
                LDSM_X4(a_lo[am], base + ALO + arow + am * 16 * 80 + kb);
            }
            #pragma unroll
            for (int pr = 0; pr < 2; pr++) {
                uint32_t b_hi[4], b_lo[4];
                LDSM_X4(b_hi, base + BHI + brow + pr * 16 * 80 + kb);
                LDSM_X4(b_lo, base + BLO + brow + pr * 16 * 80 + kb);
                #pragma unroll
                for (int od = 0; od < 2; od++) {
                    const int an = pr * 2 + od;
                    #pragma unroll
                    for (int am = 0; am < 4; am++) {
                        MMA16816(acc[am][an], a_hi[am], b_hi[od], b_hi[od + 2]);
                        MMA16816(acc[am][an], a_hi[am], b_lo[od], b_lo[od + 2]);
                        MMA16816(acc[am][an], a_lo[am], b_hi[od], b_hi[od + 2]);
                    }
                }
            }
        }
    };

    // ---- 3-stage pipeline ----
    const int nT = KDIM / 32;
    ISSUE(0, 0);
    ISSUE(32, 1);
    #pragma unroll 1
    for (int t = 0; t < nT; ++t) {
        if (t + 2 < nT) asm volatile("cp.async.wait_group 1;" ::: "memory");
        else            asm volatile("cp.async.wait_group 0;" ::: "memory");
        __syncthreads();
        if (t + 2 < nT) ISSUE((t + 2) * 32, (t + 2) % NSTAGE);
        COMPUTE(t % NSTAGE);
    }
    __syncthreads();   // done reading operand smem -> reuse as stage

    // ---- epilogue ----
    float* st = (float*)smem;
    if (IS1) {
        int* pos_s = (int*)(smem + NSTAGE * BUFB);
        // stage transposed: st[col*STG1 + row]
        #pragma unroll
        for (int am = 0; am < 4; am++)
            #pragma unroll
            for (int an = 0; an < 4; an++) {
                const int r0 = wm * 64 + am * 16 + (lane >> 2);
                const int c0 = wn * 32 + an * 8 + (lane & 3) * 2;
                st[c0 * STG1 + r0]           = acc[am][an][0];
                st[(c0 + 1) * STG1 + r0]     = acc[am][an][1];
                st[c0 * STG1 + r0 + 8]       = acc[am][an][2];
                st[(c0 + 1) * STG1 + r0 + 8] = acc[am][an][3];
            }
        if (tid < 128) pos_s[tid] = pos[b * NN + rowBase + tid];
        __syncthreads();
        // pass A: add pos-emb, write WhT hi/lo, update stage
        #pragma unroll 2
        for (int i = 0; i < 64; i++) {
            int idx = i * 512 + tid;
            int dl = idx >> 7, nl = idx & 127;
            float v = st[dl * STG1 + nl] + __ldg(pt + (long)pos_s[nl] * DOUTT + dl);
            st[dl * STG1 + nl] = v;
            __nv_bfloat16 hv = __float2bfloat16(v);
            long o = ((long)b * DOUTT + dl) * NN + rowBase + nl;
            g_WhT_hi[o] = hv;
            g_WhT_lo[o] = __float2bfloat16(v - __bfloat162float(hv));
        }
        __syncthreads();
        // pass B: fused s1/s2 (quad per node)
        {
            const int node = tid >> 2, q = tid & 3;
            float v1 = 0.f, v2 = 0.f;
            #pragma unroll 4
            for (int c = 0; c < 64; c++) {
                int dl = q * 64 + c;
                float v = st[dl * STG1 + node];
                v1 += v * __ldg(a1v + dl);
                v2 += v * __ldg(a2v + dl);
            }
            v1 += __shfl_xor_sync(0xffffffffu, v1, 1);
            v2 += __shfl_xor_sync(0xffffffffu, v2, 1);
            v1 += __shfl_xor_sync(0xffffffffu, v1, 2);
            v2 += __shfl_xor_sync(0xffffffffu, v2, 2);
            if (q == 0) {
                g_s1[b * NN + rowBase + node] = v1;
                g_s2[b * NN + rowBase + node] = v2;
            }
        }
    } else {
        // stage row-major: st[row*STG2 + col]
        #pragma unroll
        for (int am = 0; am < 4; am++)
            #pragma unroll
            for (int an = 0; an < 4; an++) {
                const int r0 = wm * 64 + am * 16 + (lane >> 2);
                const int c0 = wn * 32 + an * 8 + (lane & 3) * 2;
                st[r0 * STG2 + c0]           = acc[am][an][0];
                st[r0 * STG2 + c0 + 1]       = acc[am][an][1];
                st[(r0 + 8) * STG2 + c0]     = acc[am][an][2];
                st[(r0 + 8) * STG2 + c0 + 1] = acc[am][an][3];
            }
        __syncthreads();
        #pragma unroll 4
        for (int i = 0; i < 16; i++) {
            int fid = i * 512 + tid;
            int r = fid >> 6, c4 = fid & 63;
            float4 v = *(const float4*)&st[r * STG2 + c4 * 4];
            *(float4*)&hp[((long)b * NN + rowBase + r) * DOUTT + c4 * 4] = v;
        }
    }
}

// ---------------------------------------------------------------------------
// Masked-softmax attention row: fp32 att to d_out + hi/lo bf16 scratch.
// ---------------------------------------------------------------------------
__global__ __launch_bounds__(128)
void k_attn(const int* __restrict__ adj, float* __restrict__ att)
{
    const int i = blockIdx.x, b = blockIdx.y;
    const long base = ((long)b * NN + i) * NN;
    const int t = threadIdx.x;
    const float s1v = g_s1[b * NN + i];

    const int4   a4 = *(const int4*)(adj + base + t * 4);
    const float4 s2 = *(const float4*)(g_s2 + b * NN + t * 4);

    float e[4];
    {
        float x;
        x = s1v + s2.x; x = x > 0.f ? x : SLOPE * x; e[0] = (a4.x > 0) ? x : NEGV;
        x = s1v + s2.y; x = x > 0.f ? x : SLOPE * x; e[1] = (a4.y > 0) ? x : NEGV;
        x = s1v + s2.z; x = x > 0.f ? x : SLOPE * x; e[2] = (a4.z > 0) ? x : NEGV;
        x = s1v + s2.w; x = x > 0.f ? x : SLOPE * x; e[3] = (a4.w > 0) ? x : NEGV;
    }

    __shared__ float red[4];
    float m = fmaxf(fmaxf(e[0], e[1]), fmaxf(e[2], e[3]));
    #pragma unroll
    for (int o = 16; o; o >>= 1) m = fmaxf(m, __shfl_xor_sync(0xffffffffu, m, o));
    if ((t & 31) == 0) red[t >> 5] = m;
    __syncthreads();
    float M = fmaxf(fmaxf(red[0], red[1]), fmaxf(red[2], red[3]));
    __syncthreads();

    float x0 = __expf(e[0] - M), x1 = __expf(e[1] - M);
    float x2 = __expf(e[2] - M), x3 = __expf(e[3] - M);
    float s = (x0 + x1) + (x2 + x3);
    #pragma unroll
    for (int o = 16; o; o >>= 1) s += __shfl_xor_sync(0xffffffffu, s, o);
    if ((t & 31) == 0) red[t >> 5] = s;
    __syncthreads();
    float inv = 1.f / (red[0] + red[1] + red[2] + red[3]);

    float v0 = x0 * inv, v1 = x1 * inv, v2 = x2 * inv, v3 = x3 * inv;
    *(float4*)(att + base + t * 4) = make_float4(v0, v1, v2, v3);

    uint32_t h0 = pk2(v0, v1), h1 = pk2(v2, v3);
    uint32_t l0 = pk2(v0 - bhi(v0), v1 - bhi(v1));
    uint32_t l1 = pk2(v2 - bhi(v2), v3 - bhi(v3));
    *(uint2*)(g_att_hi + base + t * 4) = make_uint2(h0, h1);
    *(uint2*)(g_att_lo + base + t * 4) = make_uint2(l0, l1);
}

// ---------------------------------------------------------------------------
extern "C" void kernel_launch(void* const* d_in, const int* in_sizes, int n_in,
                              void* d_out, int out_size)
{
    const float* h   = (const float*)d_in[0];
    const int*   adj = (const int*)  d_in[1];
    const int*   pos = (const int*)  d_in[2];
    const float* W   = (const float*)d_in[3];
    const float* a1  = (const float*)d_in[4];
    const float* a2  = (const float*)d_in[5];
    const float* pt  = (const float*)d_in[6];

    float* out = (float*)d_out;
    float* hp  = out;                              // [B,N,DOUT]
    float* att = out + (long)BB * NN * DOUTT;      // [B,N,N]

    static int smem_set = 0;
    if (!smem_set) {
        cudaFuncSetAttribute(mma_gemm<DINN, true>,
                             cudaFuncAttributeMaxDynamicSharedMemorySize, SMEM_TOTAL);
        cudaFuncSetAttribute(mma_gemm<NN, false>,
                             cudaFuncAttributeMaxDynamicSharedMemorySize, SMEM_TOTAL);
        smem_set = 1;
    }

    dim3 gT(DINN / 32, DOUTT / 32);                // (24, 8)
    k_transW<<<gT, 256>>>(W);
    k_splitH<<<1536, 512>>>(h);

    dim3 gG(NN / 128, BB);                         // (4, 32) = 128 CTAs
    mma_gemm<DINN, true><<<gG, 512, SMEM_TOTAL>>>(pos, pt, a1, a2, nullptr);

    dim3 g3(NN, BB);                               // (512, 32)
    k_attn<<<g3, 128>>>(adj, att);

    mma_gemm<NN, false><<<gG, 512, SMEM_TOTAL>>>(nullptr, nullptr, nullptr,
                                                 nullptr, hp);
}

// round 8
// speedup vs baseline: 1.2422x; 1.2422x over previous
#include <cuda_runtime.h>
#include <cuda_fp16.h>
#include <cstdint>

#define BB 32
#define NN 512
#define DINN 768
#define DOUTT 256
#define NEGV -9.0e15f
#define SLOPE 0.2f

// ---------------------------------------------------------------------------
// Scratch (allocation-free). Referenced ONLY in device code.
// ---------------------------------------------------------------------------
__device__ __half g_h[(long)BB * NN * DINN];            // h fp16 [b][n][din]
__device__ __half g_WT_hi[DOUTT * DINN];                // W^T  [dout][din]
__device__ __half g_WT_lo[DOUTT * DINN];
__device__ __half g_WhT_hi[(long)BB * DOUTT * NN];      // Wh^T [b][dout][node]
__device__ __half g_WhT_lo[(long)BB * DOUTT * NN];
__device__ __half g_att[(long)BB * NN * NN];            // att fp16 [b][i][j]
__device__ float g_s1[BB * NN];
__device__ float g_s2[BB * NN];

// ---------------------------------------------------------------------------
__device__ __forceinline__ uint32_t smem_u32(const void* p) {
    uint32_t a;
    asm("{ .reg .u64 t; cvta.to.shared.u64 t, %1; cvt.u32.u64 %0, t; }" : "=r"(a) : "l"(p));
    return a;
}
__device__ __forceinline__ uint32_t pk2h(float a, float b) {
    __half2 hh = __floats2half2_rn(a, b);
    return *(uint32_t*)&hh;
}
__device__ __forceinline__ float hhi(float v) {
    return __half2float(__float2half_rn(v));
}
__device__ __forceinline__ void cpa16(uint32_t s, const void* g) {
    asm volatile("cp.async.cg.shared.global [%0], [%1], 16;" :: "r"(s), "l"(g));
}

#define LDSM_X4(R, A)                                                         \
    asm volatile("ldmatrix.sync.aligned.m8n8.x4.shared.b16 {%0,%1,%2,%3}, [%4];" \
        : "=r"((R)[0]), "=r"((R)[1]), "=r"((R)[2]), "=r"((R)[3]) : "r"(A))

#define MMA16816(D, A, B0, B1)                                                \
    asm volatile("mma.sync.aligned.m16n8k16.row.col.f32.f16.f16.f32 "         \
        "{%0,%1,%2,%3},{%4,%5,%6,%7},{%8,%9},{%0,%1,%2,%3};"                  \
        : "+f"((D)[0]), "+f"((D)[1]), "+f"((D)[2]), "+f"((D)[3])              \
        : "r"((A)[0]), "r"((A)[1]), "r"((A)[2]), "r"((A)[3]), "r"(B0), "r"(B1))

// per-stage operand smem: A | B_hi | B_lo ; rows stride 80 B (64B data + pad)
#define AOF 0
#define BHI 10240
#define BLO 30720
#define BUFB 51200
#define NSTAGE 3
#define STG1 132      // GEMM1 stage: st[col*132 + row], 256x132 fp32
#define STG2 264      // GEMM2 stage: st[row*264 + col], 128x264 fp32
#define SMEM_TOTAL (NSTAGE * BUFB + 512)   // 154112

// ---------------------------------------------------------------------------
// Pre-pass: W [din][dout] fp32 -> W^T hi/lo fp16 [dout][din]
// ---------------------------------------------------------------------------
__global__ __launch_bounds__(256)
void k_transW(const float* __restrict__ W)
{
    __shared__ float t[32][33];
    const int k0 = blockIdx.x * 32, n0 = blockIdx.y * 32;
    const int tx = threadIdx.x & 31, ty = threadIdx.x >> 5;
    #pragma unroll
    for (int j = 0; j < 4; j++) {
        int r = ty + j * 8;
        t[r][tx] = W[(long)(k0 + r) * DOUTT + n0 + tx];
    }
    __syncthreads();
    #pragma unroll
    for (int j = 0; j < 4; j++) {
        int r = ty + j * 8;
        float v = t[tx][r];
        __half hv = __float2half_rn(v);
        long o = (long)(n0 + r) * DINN + k0 + tx;
        g_WT_hi[o] = hv;
        g_WT_lo[o] = __float2half_rn(v - __half2float(hv));
    }
}

// ---------------------------------------------------------------------------
// Pre-pass: h fp32 -> fp16 (single plane)
// ---------------------------------------------------------------------------
__global__ __launch_bounds__(256)
void k_splitH(const float* __restrict__ h)
{
    const long total8 = (long)BB * NN * DINN / 8;
    for (long i = (long)blockIdx.x * 256 + threadIdx.x; i < total8;
         i += (long)gridDim.x * 256) {
        float4 v0 = __ldg((const float4*)h + 2 * i);
        float4 v1 = __ldg((const float4*)h + 2 * i + 1);
        uint4 o;
        o.x = pk2h(v0.x, v0.y);
        o.y = pk2h(v0.z, v0.w);
        o.z = pk2h(v1.x, v1.y);
        o.w = pk2h(v1.z, v1.w);
        *(uint4*)(g_h + i * 8) = o;
    }
}

// ---------------------------------------------------------------------------
// Warp-MMA GEMM: D[128 x 256] = A[128xK] * B^T[256xK], fp16 2-product.
// IS1: A = h fp16, B = W^T hi/lo; epi -> WhT hi/lo + s1/s2 (fused)
// !IS1: A = att fp16, B = Wh^T hi/lo; epi -> hp fp32
// grid (NN/128=4, BB); 256 threads; warps 2(M)x4(N), 64x64 per warp; 3-stage.
// ---------------------------------------------------------------------------
template<int KDIM, bool IS1>
__global__ __launch_bounds__(256, 1)
void mma_gemm(const int* __restrict__ pos, const float* __restrict__ pt,
              const float* __restrict__ a1v, const float* __restrict__ a2v,
              float* __restrict__ hp)
{
    extern __shared__ char smem[];
    const uint32_t sbase = smem_u32(smem);
    const int tid = threadIdx.x;
    const int lane = tid & 31, wid = tid >> 5;
    const int wm = wid & 1, wn = wid >> 1;
    const int b = blockIdx.y;
    const int rowBase = blockIdx.x * 128;

    const __half* Ag  = IS1 ? g_h : g_att;
    const __half* Bgh = IS1 ? g_WT_hi : g_WhT_hi;
    const __half* Bgl = IS1 ? g_WT_lo : g_WhT_lo;
    const int AK = IS1 ? DINN : NN;

    float acc[4][8][4];
    #pragma unroll
    for (int i = 0; i < 4; i++)
        #pragma unroll
        for (int j = 0; j < 8; j++)
            #pragma unroll
            for (int r = 0; r < 4; r++) acc[i][j][r] = 0.f;

    auto ISSUE = [&](int kc, int s) {
        const uint32_t sb2 = sbase + s * BUFB;
        #pragma unroll
        for (int i = 0; i < 2; i++) {   // A: 128 rows x 64 B
            int idx = i * 256 + tid;
            int r = idx >> 2, c4 = idx & 3;
            long go = ((long)b * NN + rowBase + r) * (long)AK + kc + c4 * 8;
            cpa16(sb2 + AOF + r * 80 + c4 * 16, Ag + go);
        }
        #pragma unroll
        for (int i = 0; i < 4; i++) {   // B: 256 rows x 64 B, hi+lo
            int idx = i * 256 + tid;
            int r = idx >> 2, c4 = idx & 3;
            long go = IS1 ? ((long)r * DINN + kc + c4 * 8)
                          : (((long)b * DOUTT + r) * NN + kc + c4 * 8);
            uint32_t so = r * 80 + c4 * 16;
            cpa16(sb2 + BHI + so, Bgh + go);
            cpa16(sb2 + BLO + so, Bgl + go);
        }
        asm volatile("cp.async.commit_group;" ::: "memory");
    };

    const int arow = (wm * 64 + ((lane >> 3) & 1) * 8 + (lane & 7)) * 80;
    const int brow = (wn * 64 + ((lane >> 3) & 1) * 8 + (lane & 7)) * 80;

    auto COMPUTE = [&](int s) {
        const uint32_t base = sbase + s * BUFB;
        #pragma unroll
        for (int k16 = 0; k16 < 2; k16++) {
            const int kb = (k16 * 16 + (lane >> 4) * 8) * 2;
            uint32_t af[4][4];
            #pragma unroll
            for (int am = 0; am < 4; am++)
                LDSM_X4(af[am], base + AOF + arow + am * 16 * 80 + kb);
            #pragma unroll
            for (int pr = 0; pr < 4; pr++) {
                uint32_t b_hi[4], b_lo[4];
                LDSM_X4(b_hi, base + BHI + brow + pr * 16 * 80 + kb);
                LDSM_X4(b_lo, base + BLO + brow + pr * 16 * 80 + kb);
                #pragma unroll
                for (int od = 0; od < 2; od++) {
                    const int an = pr * 2 + od;
                    #pragma unroll
                    for (int am = 0; am < 4; am++) {
                        MMA16816(acc[am][an], af[am], b_hi[od], b_hi[od + 2]);
                        MMA16816(acc[am][an], af[am], b_lo[od], b_lo[od + 2]);
                    }
                }
            }
        }
    };

    // ---- 3-stage pipeline, one sync per k-tile ----
    const int nT = KDIM / 32;
    ISSUE(0, 0);
    ISSUE(32, 1);
    #pragma unroll 1
    for (int t = 0; t < nT; ++t) {
        if (t + 2 < nT) asm volatile("cp.async.wait_group 1;" ::: "memory");
        else            asm volatile("cp.async.wait_group 0;" ::: "memory");
        __syncthreads();
        if (t + 2 < nT) ISSUE((t + 2) * 32, (t + 2) % NSTAGE);
        COMPUTE(t % NSTAGE);
    }
    __syncthreads();   // done reading operand smem -> reuse as stage

    // ---- epilogue ----
    float* st = (float*)smem;
    if (IS1) {
        int* pos_s = (int*)(smem + NSTAGE * BUFB);
        // stage transposed: st[col*STG1 + row]
        #pragma unroll
        for (int am = 0; am < 4; am++)
            #pragma unroll
            for (int an = 0; an < 8; an++) {
                const int r0 = wm * 64 + am * 16 + (lane >> 2);
                const int c0 = wn * 64 + an * 8 + (lane & 3) * 2;
                st[c0 * STG1 + r0]           = acc[am][an][0];
                st[(c0 + 1) * STG1 + r0]     = acc[am][an][1];
                st[c0 * STG1 + r0 + 8]       = acc[am][an][2];
                st[(c0 + 1) * STG1 + r0 + 8] = acc[am][an][3];
            }
        if (tid < 128) pos_s[tid] = pos[b * NN + rowBase + tid];
        __syncthreads();
        // pass A: add pos-emb, write WhT hi/lo, update stage
        #pragma unroll 2
        for (int i = 0; i < 128; i++) {
            int idx = i * 256 + tid;
            int dl = idx >> 7, nl = idx & 127;
            float v = st[dl * STG1 + nl] + __ldg(pt + (long)pos_s[nl] * DOUTT + dl);
            st[dl * STG1 + nl] = v;
            __half hv = __float2half_rn(v);
            long o = ((long)b * DOUTT + dl) * NN + rowBase + nl;
            g_WhT_hi[o] = hv;
            g_WhT_lo[o] = __float2half_rn(v - __half2float(hv));
        }
        __syncthreads();
        // pass B: fused s1/s2 (pair per node)
        {
            const int node = tid >> 1, half = tid & 1;
            float v1 = 0.f, v2 = 0.f;
            #pragma unroll 4
            for (int c = 0; c < 128; c++) {
                int dl = half * 128 + c;
                float v = st[dl * STG1 + node];
                v1 += v * __ldg(a1v + dl);
                v2 += v * __ldg(a2v + dl);
            }
            v1 += __shfl_down_sync(0xffffffffu, v1, 1);
            v2 += __shfl_down_sync(0xffffffffu, v2, 1);
            if (half == 0) {
                g_s1[b * NN + rowBase + node] = v1;
                g_s2[b * NN + rowBase + node] = v2;
            }
        }
    } else {
        // stage row-major: st[row*STG2 + col]
        #pragma unroll
        for (int am = 0; am < 4; am++)
            #pragma unroll
            for (int an = 0; an < 8; an++) {
                const int r0 = wm * 64 + am * 16 + (lane >> 2);
                const int c0 = wn * 64 + an * 8 + (lane & 3) * 2;
                st[r0 * STG2 + c0]           = acc[am][an][0];
                st[r0 * STG2 + c0 + 1]       = acc[am][an][1];
                st[(r0 + 8) * STG2 + c0]     = acc[am][an][2];
                st[(r0 + 8) * STG2 + c0 + 1] = acc[am][an][3];
            }
        __syncthreads();
        #pragma unroll 4
        for (int i = 0; i < 32; i++) {
            int fid = i * 256 + tid;
            int r = fid >> 6, c4 = fid & 63;
            float4 v = *(const float4*)&st[r * STG2 + c4 * 4];
            *(float4*)&hp[((long)b * NN + rowBase + r) * DOUTT + c4 * 4] = v;
        }
    }
}

// ---------------------------------------------------------------------------
// Masked-softmax attention row: fp32 att to d_out + fp16 scratch.
// ---------------------------------------------------------------------------
__global__ __launch_bounds__(128)
void k_attn(const int* __restrict__ adj, float* __restrict__ att)
{
    const int i = blockIdx.x, b = blockIdx.y;
    const long base = ((long)b * NN + i) * NN;
    const int t = threadIdx.x;
    const float s1v = g_s1[b * NN + i];

    const int4   a4 = *(const int4*)(adj + base + t * 4);
    const float4 s2 = *(const float4*)(g_s2 + b * NN + t * 4);

    float e[4];
    {
        float x;
        x = s1v + s2.x; x = x > 0.f ? x : SLOPE * x; e[0] = (a4.x > 0) ? x : NEGV;
        x = s1v + s2.y; x = x > 0.f ? x : SLOPE * x; e[1] = (a4.y > 0) ? x : NEGV;
        x = s1v + s2.z; x = x > 0.f ? x : SLOPE * x; e[2] = (a4.z > 0) ? x : NEGV;
        x = s1v + s2.w; x = x > 0.f ? x : SLOPE * x; e[3] = (a4.w > 0) ? x : NEGV;
    }

    __shared__ float red[4];
    float m = fmaxf(fmaxf(e[0], e[1]), fmaxf(e[2], e[3]));
    #pragma unroll
    for (int o = 16; o; o >>= 1) m = fmaxf(m, __shfl_xor_sync(0xffffffffu, m, o));
    if ((t & 31) == 0) red[t >> 5] = m;
    __syncthreads();
    float M = fmaxf(fmaxf(red[0], red[1]), fmaxf(red[2], red[3]));
    __syncthreads();

    float x0 = __expf(e[0] - M), x1 = __expf(e[1] - M);
    float x2 = __expf(e[2] - M), x3 = __expf(e[3] - M);
    float s = (x0 + x1) + (x2 + x3);
    #pragma unroll
    for (int o = 16; o; o >>= 1) s += __shfl_xor_sync(0xffffffffu, s, o);
    if ((t & 31) == 0) red[t >> 5] = s;
    __syncthreads();
    float inv = 1.f / (red[0] + red[1] + red[2] + red[3]);

    float v0 = x0 * inv, v1 = x1 * inv, v2 = x2 * inv, v3 = x3 * inv;
    *(float4*)(att + base + t * 4) = make_float4(v0, v1, v2, v3);
    *(uint2*)(g_att + base + t * 4) = make_uint2(pk2h(v0, v1), pk2h(v2, v3));
}

// ---------------------------------------------------------------------------
extern "C" void kernel_launch(void* const* d_in, const int* in_sizes, int n_in,
                              void* d_out, int out_size)
{
    const float* h   = (const float*)d_in[0];
    const int*   adj = (const int*)  d_in[1];
    const int*   pos = (const int*)  d_in[2];
    const float* W   = (const float*)d_in[3];
    const float* a1  = (const float*)d_in[4];
    const float* a2  = (const float*)d_in[5];
    const float* pt  = (const float*)d_in[6];

    float* out = (float*)d_out;
    float* hp  = out;                              // [B,N,DOUT]
    float* att = out + (long)BB * NN * DOUTT;      // [B,N,N]

    static int smem_set = 0;
    if (!smem_set) {
        cudaFuncSetAttribute(mma_gemm<DINN, true>,
                             cudaFuncAttributeMaxDynamicSharedMemorySize, SMEM_TOTAL);
        cudaFuncSetAttribute(mma_gemm<NN, false>,
                             cudaFuncAttributeMaxDynamicSharedMemorySize, SMEM_TOTAL);
        smem_set = 1;
    }

    dim3 gT(DINN / 32, DOUTT / 32);                // (24, 8)
    k_transW<<<gT, 256>>>(W);
    k_splitH<<<2048, 256>>>(h);

    dim3 gG(NN / 128, BB);                         // (4, 32) = 128 CTAs
    mma_gemm<DINN, true><<<gG, 256, SMEM_TOTAL>>>(pos, pt, a1, a2, nullptr);

    dim3 g3(NN, BB);                               // (512, 32)
    k_attn<<<g3, 128>>>(adj, att);

    mma_gemm<NN, false><<<gG, 256, SMEM_TOTAL>>>(nullptr, nullptr, nullptr,
                                                 nullptr, hp);
}

// round 9
// speedup vs baseline: 1.4186x; 1.1421x over previous
#include <cuda_runtime.h>
#include <cuda_fp16.h>
#include <cstdint>

#define BB 32
#define NN 512
#define DINN 768
#define DOUTT 256
#define NEGV -9.0e15f
#define SLOPE 0.2f

// ---------------------------------------------------------------------------
// Scratch (allocation-free). Referenced ONLY in device code.
// ---------------------------------------------------------------------------
__device__ __half g_h[(long)BB * NN * DINN];            // h fp16 [b][n][din]
__device__ __half g_WT_hi[DOUTT * DINN];                // W^T  [dout][din]
__device__ __half g_WT_lo[DOUTT * DINN];
__device__ __half g_WhT[(long)BB * DOUTT * NN];         // Wh^T fp16 [b][dout][node]
__device__ __half g_att[(long)BB * NN * NN];            // att fp16 [b][i][j]
__device__ float g_s1[BB * NN];
__device__ float g_s2[BB * NN];

// ---------------------------------------------------------------------------
__device__ __forceinline__ uint32_t smem_u32(const void* p) {
    uint32_t a;
    asm("{ .reg .u64 t; cvta.to.shared.u64 t, %1; cvt.u32.u64 %0, t; }" : "=r"(a) : "l"(p));
    return a;
}
__device__ __forceinline__ uint32_t pk2h(float a, float b) {
    __half2 hh = __floats2half2_rn(a, b);
    return *(uint32_t*)&hh;
}
__device__ __forceinline__ void cpa16(uint32_t s, const void* g) {
    asm volatile("cp.async.cg.shared.global [%0], [%1], 16;" :: "r"(s), "l"(g));
}

#define LDSM_X4(R, A)                                                         \
    asm volatile("ldmatrix.sync.aligned.m8n8.x4.shared.b16 {%0,%1,%2,%3}, [%4];" \
        : "=r"((R)[0]), "=r"((R)[1]), "=r"((R)[2]), "=r"((R)[3]) : "r"(A))

#define MMA16816(D, A, B0, B1)                                                \
    asm volatile("mma.sync.aligned.m16n8k16.row.col.f32.f16.f16.f32 "         \
        "{%0,%1,%2,%3},{%4,%5,%6,%7},{%8,%9},{%0,%1,%2,%3};"                  \
        : "+f"((D)[0]), "+f"((D)[1]), "+f"((D)[2]), "+f"((D)[3])              \
        : "r"((A)[0]), "r"((A)[1]), "r"((A)[2]), "r"((A)[3]), "r"(B0), "r"(B1))

// G1: A(64x32 fp16) | B_hi(256x32) | B_lo(256x32), rows stride 80 B
#define G1_A   0
#define G1_BH  5120
#define G1_BL  25600
#define G1_BUF 46080
#define G1_SMEM 92672          // 2 stages (92160) + pos_s(256) -> 2 CTAs/SM
// G2: A(64x32) | B_hi(256x32)
#define G2_A   0
#define G2_BH  5120
#define G2_BUF 25600
#define G2_SMEM 76800          // 3 stages; epilogue stage 67584 fits
#define STG1 68                // G1 stage: st[dout*68 + node], 256x64
#define STG2 264               // G2 stage: st[node*264 + dout], 64x256

// ---------------------------------------------------------------------------
// Pre-pass: W [din][dout] fp32 -> W^T hi/lo fp16 [dout][din]
// ---------------------------------------------------------------------------
__global__ __launch_bounds__(256)
void k_transW(const float* __restrict__ W)
{
    __shared__ float t[32][33];
    const int k0 = blockIdx.x * 32, n0 = blockIdx.y * 32;
    const int tx = threadIdx.x & 31, ty = threadIdx.x >> 5;
    #pragma unroll
    for (int j = 0; j < 4; j++) {
        int r = ty + j * 8;
        t[r][tx] = W[(long)(k0 + r) * DOUTT + n0 + tx];
    }
    __syncthreads();
    #pragma unroll
    for (int j = 0; j < 4; j++) {
        int r = ty + j * 8;
        float v = t[tx][r];
        __half hv = __float2half_rn(v);
        long o = (long)(n0 + r) * DINN + k0 + tx;
        g_WT_hi[o] = hv;
        g_WT_lo[o] = __float2half_rn(v - __half2float(hv));
    }
}

// ---------------------------------------------------------------------------
// Pre-pass: h fp32 -> fp16
// ---------------------------------------------------------------------------
__global__ __launch_bounds__(256)
void k_splitH(const float* __restrict__ h)
{
    const long total8 = (long)BB * NN * DINN / 8;
    for (long i = (long)blockIdx.x * 256 + threadIdx.x; i < total8;
         i += (long)gridDim.x * 256) {
        float4 v0 = __ldg((const float4*)h + 2 * i);
        float4 v1 = __ldg((const float4*)h + 2 * i + 1);
        uint4 o;
        o.x = pk2h(v0.x, v0.y);
        o.y = pk2h(v0.z, v0.w);
        o.z = pk2h(v1.x, v1.y);
        o.w = pk2h(v1.z, v1.w);
        *(uint4*)(g_h + i * 8) = o;
    }
}

// ---------------------------------------------------------------------------
// GEMM1: D[64 x 256] = h[64xK] * W^T (hi+lo), K=768.
// 2-stage cp.async ring, one sync/iter. Epilogue: WhT fp16 + fused s1/s2.
// grid (NN/64=8, BB) = 256 CTAs; 8 warps of 64x32 (1M x 8N).
// ---------------------------------------------------------------------------
__global__ __launch_bounds__(256, 2)
void g1_gemm(const int* __restrict__ pos, const float* __restrict__ pt,
             const float* __restrict__ a1v, const float* __restrict__ a2v)
{
    extern __shared__ char smem[];
    const uint32_t sbase = smem_u32(smem);
    const int tid = threadIdx.x, lane = tid & 31, wid = tid >> 5;
    const int b = blockIdx.y;
    const int rowBase = blockIdx.x * 64;

    float acc[4][4][4];
    #pragma unroll
    for (int i = 0; i < 4; i++)
        #pragma unroll
        for (int j = 0; j < 4; j++)
            #pragma unroll
            for (int r = 0; r < 4; r++) acc[i][j][r] = 0.f;

    auto ISSUE = [&](int kc, int s) {
        const uint32_t sb2 = sbase + s * G1_BUF;
        {   // A: 64 rows x 64 B
            int r = tid >> 2, c4 = tid & 3;
            long go = ((long)b * NN + rowBase + r) * DINN + kc + c4 * 8;
            cpa16(sb2 + G1_A + r * 80 + c4 * 16, g_h + go);
        }
        #pragma unroll
        for (int i = 0; i < 4; i++) {   // B: 256 rows x 64 B, hi+lo
            int idx = i * 256 + tid;
            int r = idx >> 2, c4 = idx & 3;
            long go = (long)r * DINN + kc + c4 * 8;
            uint32_t so = r * 80 + c4 * 16;
            cpa16(sb2 + G1_BH + so, g_WT_hi + go);
            cpa16(sb2 + G1_BL + so, g_WT_lo + go);
        }
        asm volatile("cp.async.commit_group;" ::: "memory");
    };

    const int arow = (((lane >> 3) & 1) * 8 + (lane & 7)) * 80;
    const int brow = (wid * 32 + ((lane >> 3) & 1) * 8 + (lane & 7)) * 80;

    auto COMPUTE = [&](int s) {
        const uint32_t base = sbase + s * G1_BUF;
        #pragma unroll
        for (int k16 = 0; k16 < 2; k16++) {
            const int kb = (k16 * 16 + (lane >> 4) * 8) * 2;
            uint32_t af[4][4];
            #pragma unroll
            for (int am = 0; am < 4; am++)
                LDSM_X4(af[am], base + G1_A + arow + am * 16 * 80 + kb);
            #pragma unroll
            for (int pr = 0; pr < 2; pr++) {
                uint32_t bh[4], bl[4];
                LDSM_X4(bh, base + G1_BH + brow + pr * 16 * 80 + kb);
                LDSM_X4(bl, base + G1_BL + brow + pr * 16 * 80 + kb);
                #pragma unroll
                for (int od = 0; od < 2; od++) {
                    const int an = pr * 2 + od;
                    #pragma unroll
                    for (int am = 0; am < 4; am++) {
                        MMA16816(acc[am][an], af[am], bh[od], bh[od + 2]);
                        MMA16816(acc[am][an], af[am], bl[od], bl[od + 2]);
                    }
                }
            }
        }
    };

    // 2-stage, single sync per iter: top-of-loop sync orders buffer reuse.
    const int nT = DINN / 32;     // 24
    ISSUE(0, 0);
    #pragma unroll 1
    for (int t = 0; t < nT; ++t) {
        asm volatile("cp.async.wait_group 0;" ::: "memory");
        __syncthreads();
        if (t + 1 < nT) ISSUE((t + 1) * 32, (t + 1) & 1);
        COMPUTE(t & 1);
    }
    __syncthreads();

    // ---- epilogue ----
    float* st  = (float*)smem;                 // [256 dout][68] x fp32
    float* ps1 = (float*)(smem + 69632);       // [4][64]
    float* ps2 = (float*)(smem + 70656);
    int* pos_s = (int*)(smem + 2 * G1_BUF);    // 64 ints

    #pragma unroll
    for (int am = 0; am < 4; am++)
        #pragma unroll
        for (int an = 0; an < 4; an++) {
            const int r0 = am * 16 + (lane >> 2);
            const int c0 = wid * 32 + an * 8 + (lane & 3) * 2;
            st[c0 * STG1 + r0]           = acc[am][an][0];
            st[(c0 + 1) * STG1 + r0]     = acc[am][an][1];
            st[c0 * STG1 + r0 + 8]       = acc[am][an][2];
            st[(c0 + 1) * STG1 + r0 + 8] = acc[am][an][3];
        }
    if (tid < 64) pos_s[tid] = pos[b * NN + rowBase + tid];
    __syncthreads();

    // pass A: add pos-emb, write WhT fp16, update stage
    #pragma unroll 2
    for (int i = 0; i < 64; i++) {
        int idx = i * 256 + tid;
        int dl = idx >> 6, nl = idx & 63;
        float v = st[dl * STG1 + nl] + __ldg(pt + (long)pos_s[nl] * DOUTT + dl);
        st[dl * STG1 + nl] = v;
        g_WhT[((long)b * DOUTT + dl) * NN + rowBase + nl] = __float2half_rn(v);
    }
    __syncthreads();

    // pass B: fused s1/s2
    {
        const int node = tid & 63, q = tid >> 6;
        float v1 = 0.f, v2 = 0.f;
        #pragma unroll 4
        for (int c = 0; c < 64; c++) {
            int dl = q * 64 + c;
            float v = st[dl * STG1 + node];
            v1 += v * __ldg(a1v + dl);
            v2 += v * __ldg(a2v + dl);
        }
        ps1[q * 64 + node] = v1;
        ps2[q * 64 + node] = v2;
    }
    __syncthreads();
    if (tid < 64) {
        float s1 = ps1[tid] + ps1[64 + tid] + ps1[128 + tid] + ps1[192 + tid];
        float s2 = ps2[tid] + ps2[64 + tid] + ps2[128 + tid] + ps2[192 + tid];
        g_s1[b * NN + rowBase + tid] = s1;
        g_s2[b * NN + rowBase + tid] = s2;
    }
}

// ---------------------------------------------------------------------------
// GEMM2: hp[64 x 256] = att[64xK] * WhT, K=512, single fp16 product.
// 3-stage ring, one sync/iter. grid (8, BB); 8 warps of 64x32.
// ---------------------------------------------------------------------------
__global__ __launch_bounds__(256, 2)
void g2_gemm(float* __restrict__ hp)
{
    extern __shared__ char smem[];
    const uint32_t sbase = smem_u32(smem);
    const int tid = threadIdx.x, lane = tid & 31, wid = tid >> 5;
    const int b = blockIdx.y;
    const int rowBase = blockIdx.x * 64;

    float acc[4][4][4];
    #pragma unroll
    for (int i = 0; i < 4; i++)
        #pragma unroll
        for (int j = 0; j < 4; j++)
            #pragma unroll
            for (int r = 0; r < 4; r++) acc[i][j][r] = 0.f;

    auto ISSUE = [&](int kc, int s) {
        const uint32_t sb2 = sbase + s * G2_BUF;
        {   // A: att 64 rows x 64 B
            int r = tid >> 2, c4 = tid & 3;
            long go = ((long)b * NN + rowBase + r) * NN + kc + c4 * 8;
            cpa16(sb2 + G2_A + r * 80 + c4 * 16, g_att + go);
        }
        #pragma unroll
        for (int i = 0; i < 4; i++) {   // B: WhT 256 rows x 64 B
            int idx = i * 256 + tid;
            int r = idx >> 2, c4 = idx & 3;
            long go = ((long)b * DOUTT + r) * NN + kc + c4 * 8;
            cpa16(sb2 + G2_BH + r * 80 + c4 * 16, g_WhT + go);
        }
        asm volatile("cp.async.commit_group;" ::: "memory");
    };

    const int arow = (((lane >> 3) & 1) * 8 + (lane & 7)) * 80;
    const int brow = (wid * 32 + ((lane >> 3) & 1) * 8 + (lane & 7)) * 80;

    auto COMPUTE = [&](int s) {
        const uint32_t base = sbase + s * G2_BUF;
        #pragma unroll
        for (int k16 = 0; k16 < 2; k16++) {
            const int kb = (k16 * 16 + (lane >> 4) * 8) * 2;
            uint32_t af[4][4];
            #pragma unroll
            for (int am = 0; am < 4; am++)
                LDSM_X4(af[am], base + G2_A + arow + am * 16 * 80 + kb);
            #pragma unroll
            for (int pr = 0; pr < 2; pr++) {
                uint32_t bh[4];
                LDSM_X4(bh, base + G2_BH + brow + pr * 16 * 80 + kb);
                #pragma unroll
                for (int od = 0; od < 2; od++) {
                    const int an = pr * 2 + od;
                    #pragma unroll
                    for (int am = 0; am < 4; am++)
                        MMA16816(acc[am][an], af[am], bh[od], bh[od + 2]);
                }
            }
        }
    };

    const int nT = NN / 32;       // 16
    ISSUE(0, 0);
    ISSUE(32, 1);
    #pragma unroll 1
    for (int t = 0; t < nT; ++t) {
        if (t + 2 < nT) asm volatile("cp.async.wait_group 1;" ::: "memory");
        else            asm volatile("cp.async.wait_group 0;" ::: "memory");
        __syncthreads();
        if (t + 2 < nT) ISSUE((t + 2) * 32, (t + 2) % 3);
        COMPUTE(t % 3);
    }
    __syncthreads();

    // ---- epilogue: stage row-major, coalesced float4 out ----
    float* st = (float*)smem;
    #pragma unroll
    for (int am = 0; am < 4; am++)
        #pragma unroll
        for (int an = 0; an < 4; an++) {
            const int r0 = am * 16 + (lane >> 2);
            const int c0 = wid * 32 + an * 8 + (lane & 3) * 2;
            st[r0 * STG2 + c0]           = acc[am][an][0];
            st[r0 * STG2 + c0 + 1]       = acc[am][an][1];
            st[(r0 + 8) * STG2 + c0]     = acc[am][an][2];
            st[(r0 + 8) * STG2 + c0 + 1] = acc[am][an][3];
        }
    __syncthreads();
    #pragma unroll 4
    for (int i = 0; i < 16; i++) {
        int fid = i * 256 + tid;
        int r = fid >> 6, c4 = fid & 63;
        float4 v = *(const float4*)&st[r * STG2 + c4 * 4];
        *(float4*)&hp[((long)b * NN + rowBase + r) * DOUTT + c4 * 4] = v;
    }
}

// ---------------------------------------------------------------------------
// Masked-softmax attention row: fp32 att to d_out + fp16 scratch.
// ---------------------------------------------------------------------------
__global__ __launch_bounds__(128)
void k_attn(const int* __restrict__ adj, float* __restrict__ att)
{
    const int i = blockIdx.x, b = blockIdx.y;
    const long base = ((long)b * NN + i) * NN;
    const int t = threadIdx.x;
    const float s1v = g_s1[b * NN + i];

    const int4   a4 = *(const int4*)(adj + base + t * 4);
    const float4 s2 = *(const float4*)(g_s2 + b * NN + t * 4);

    float e[4];
    {
        float x;
        x = s1v + s2.x; x = x > 0.f ? x : SLOPE * x; e[0] = (a4.x > 0) ? x : NEGV;
        x = s1v + s2.y; x = x > 0.f ? x : SLOPE * x; e[1] = (a4.y > 0) ? x : NEGV;
        x = s1v + s2.z; x = x > 0.f ? x : SLOPE * x; e[2] = (a4.z > 0) ? x : NEGV;
        x = s1v + s2.w; x = x > 0.f ? x : SLOPE * x; e[3] = (a4.w > 0) ? x : NEGV;
    }

    __shared__ float red[4];
    float m = fmaxf(fmaxf(e[0], e[1]), fmaxf(e[2], e[3]));
    #pragma unroll
    for (int o = 16; o; o >>= 1) m = fmaxf(m, __shfl_xor_sync(0xffffffffu, m, o));
    if ((t & 31) == 0) red[t >> 5] = m;
    __syncthreads();
    float M = fmaxf(fmaxf(red[0], red[1]), fmaxf(red[2], red[3]));
    __syncthreads();

    float x0 = __expf(e[0] - M), x1 = __expf(e[1] - M);
    float x2 = __expf(e[2] - M), x3 = __expf(e[3] - M);
    float s = (x0 + x1) + (x2 + x3);
    #pragma unroll
    for (int o = 16; o; o >>= 1) s += __shfl_xor_sync(0xffffffffu, s, o);
    if ((t & 31) == 0) red[t >> 5] = s;
    __syncthreads();
    float inv = 1.f / (red[0] + red[1] + red[2] + red[3]);

    float v0 = x0 * inv, v1 = x1 * inv, v2 = x2 * inv, v3 = x3 * inv;
    *(float4*)(att + base + t * 4) = make_float4(v0, v1, v2, v3);
    *(uint2*)(g_att + base + t * 4) = make_uint2(pk2h(v0, v1), pk2h(v2, v3));
}

// ---------------------------------------------------------------------------
extern "C" void kernel_launch(void* const* d_in, const int* in_sizes, int n_in,
                              void* d_out, int out_size)
{
    const float* h   = (const float*)d_in[0];
    const int*   adj = (const int*)  d_in[1];
    const int*   pos = (const int*)  d_in[2];
    const float* W   = (const float*)d_in[3];
    const float* a1  = (const float*)d_in[4];
    const float* a2  = (const float*)d_in[5];
    const float* pt  = (const float*)d_in[6];

    float* out = (float*)d_out;
    float* hp  = out;                              // [B,N,DOUT]
    float* att = out + (long)BB * NN * DOUTT;      // [B,N,N]

    static int smem_set = 0;
    if (!smem_set) {
        cudaFuncSetAttribute(g1_gemm, cudaFuncAttributeMaxDynamicSharedMemorySize, G1_SMEM);
        cudaFuncSetAttribute(g2_gemm, cudaFuncAttributeMaxDynamicSharedMemorySize, G2_SMEM);
        smem_set = 1;
    }

    dim3 gT(DINN / 32, DOUTT / 32);                // (24, 8)
    k_transW<<<gT, 256>>>(W);
    k_splitH<<<2048, 256>>>(h);

    dim3 gG(NN / 64, BB);                          // (8, 32) = 256 CTAs
    g1_gemm<<<gG, 256, G1_SMEM>>>(pos, pt, a1, a2);

    dim3 g3(NN, BB);                               // (512, 32)
    k_attn<<<g3, 128>>>(adj, att);

    g2_gemm<<<gG, 256, G2_SMEM>>>(hp);
}

// round 10
// speedup vs baseline: 1.5887x; 1.1199x over previous
#include <cuda_runtime.h>
#include <cuda_fp16.h>
#include <cstdint>

#define BB 32
#define NN 512
#define DINN 768
#define DOUTT 256
#define NEGV -9.0e15f
#define SLOPE 0.2f

// ---------------------------------------------------------------------------
// Scratch (allocation-free). Referenced ONLY in device code.
// ---------------------------------------------------------------------------
__device__ __half g_WT_hi[DOUTT * DINN];                // W^T  [dout][din]
__device__ __half g_WT_lo[DOUTT * DINN];
__device__ __half g_WhT[(long)BB * DOUTT * NN];         // Wh^T fp16 [b][dout][node]
__device__ __half g_att[(long)BB * NN * NN];            // att fp16 [b][i][j]
__device__ float g_s1[BB * NN];
__device__ float g_s2[BB * NN];

// ---------------------------------------------------------------------------
__device__ __forceinline__ uint32_t smem_u32(const void* p) {
    uint32_t a;
    asm("{ .reg .u64 t; cvta.to.shared.u64 t, %1; cvt.u32.u64 %0, t; }" : "=r"(a) : "l"(p));
    return a;
}
__device__ __forceinline__ uint32_t pk2h(float a, float b) {
    __half2 hh = __floats2half2_rn(a, b);
    return *(uint32_t*)&hh;
}
__device__ __forceinline__ void cpa16(uint32_t s, const void* g) {
    asm volatile("cp.async.cg.shared.global [%0], [%1], 16;" :: "r"(s), "l"(g));
}

#define LDSM_X4(R, A)                                                         \
    asm volatile("ldmatrix.sync.aligned.m8n8.x4.shared.b16 {%0,%1,%2,%3}, [%4];" \
        : "=r"((R)[0]), "=r"((R)[1]), "=r"((R)[2]), "=r"((R)[3]) : "r"(A))

#define MMA16816(D, A, B0, B1)                                                \
    asm volatile("mma.sync.aligned.m16n8k16.row.col.f32.f16.f16.f32 "         \
        "{%0,%1,%2,%3},{%4,%5,%6,%7},{%8,%9},{%0,%1,%2,%3};"                  \
        : "+f"((D)[0]), "+f"((D)[1]), "+f"((D)[2]), "+f"((D)[3])              \
        : "r"((A)[0]), "r"((A)[1]), "r"((A)[2]), "r"((A)[3]), "r"(B0), "r"(B1))

// G1: A(64x32 fp16) | B_hi(256x32) | B_lo(256x32), rows stride 80 B
#define G1_A   0
#define G1_BH  5120
#define G1_BL  25600
#define G1_BUF 46080
#define G1_SMEM 92672          // 2 stages (92160) + pos_s(256) -> 2 CTAs/SM
// G2: A(64x32) | B_hi(256x32)
#define G2_A   0
#define G2_BH  5120
#define G2_BUF 25600
#define G2_SMEM 76800          // 3 stages; epilogue stage 67584 fits
#define STG1 68                // G1 stage: st[dout*68 + node], 256x64
#define STG2 264               // G2 stage: st[node*264 + dout], 64x256

// ---------------------------------------------------------------------------
// Pre-pass: W [din][dout] fp32 -> W^T hi/lo fp16 [dout][din]
// ---------------------------------------------------------------------------
__global__ __launch_bounds__(256)
void k_transW(const float* __restrict__ W)
{
    __shared__ float t[32][33];
    const int k0 = blockIdx.x * 32, n0 = blockIdx.y * 32;
    const int tx = threadIdx.x & 31, ty = threadIdx.x >> 5;
    #pragma unroll
    for (int j = 0; j < 4; j++) {
        int r = ty + j * 8;
        t[r][tx] = W[(long)(k0 + r) * DOUTT + n0 + tx];
    }
    __syncthreads();
    #pragma unroll
    for (int j = 0; j < 4; j++) {
        int r = ty + j * 8;
        float v = t[tx][r];
        __half hv = __float2half_rn(v);
        long o = (long)(n0 + r) * DINN + k0 + tx;
        g_WT_hi[o] = hv;
        g_WT_lo[o] = __float2half_rn(v - __half2float(hv));
    }
}

// ---------------------------------------------------------------------------
// GEMM1: D[64 x 256] = h[64xK] * W^T (hi+lo), K=768.
// A converted fp32->fp16 inline (register-staged); B via cp.async.
// 2-stage ring, one sync/iter. Epilogue: WhT fp16 + fused s1/s2.
// grid (NN/64=8, BB) = 256 CTAs; 8 warps of 64x32 (1M x 8N).
// ---------------------------------------------------------------------------
__global__ __launch_bounds__(256, 2)
void g1_gemm(const float* __restrict__ hsrc,
             const int* __restrict__ pos, const float* __restrict__ pt,
             const float* __restrict__ a1v, const float* __restrict__ a2v)
{
    extern __shared__ char smem[];
    const uint32_t sbase = smem_u32(smem);
    const int tid = threadIdx.x, lane = tid & 31, wid = tid >> 5;
    const int b = blockIdx.y;
    const int rowBase = blockIdx.x * 64;

    float acc[4][4][4];
    #pragma unroll
    for (int i = 0; i < 4; i++)
        #pragma unroll
        for (int j = 0; j < 4; j++)
            #pragma unroll
            for (int r = 0; r < 4; r++) acc[i][j][r] = 0.f;

    // A register staging: 2 float4 per thread per stage (8 regs)
    //   idx = i*256 + tid ; row = idx>>3 (0..63), c4 = idx&7 (float4 along k)
    const float* Abase = hsrc + ((long)b * NN + rowBase) * DINN;
    float4 fa[2];

    auto ALOADR = [&](int kc) {
        #pragma unroll
        for (int i = 0; i < 2; i++) {
            int idx = i * 256 + tid;
            int r = idx >> 3, c4 = idx & 7;
            fa[i] = *(const float4*)(Abase + (long)r * DINN + kc + c4 * 4);
        }
    };
    auto ASTORE = [&](int s) {
        char* bufc = smem + s * G1_BUF;
        #pragma unroll
        for (int i = 0; i < 2; i++) {
            int idx = i * 256 + tid;
            int r = idx >> 3, c4 = idx & 7;
            *(uint2*)(bufc + G1_A + r * 80 + c4 * 8) =
                make_uint2(pk2h(fa[i].x, fa[i].y), pk2h(fa[i].z, fa[i].w));
        }
    };
    auto ISSUE_B = [&](int kc, int s) {
        const uint32_t sb2 = sbase + s * G1_BUF;
        #pragma unroll
        for (int i = 0; i < 4; i++) {   // B: 256 rows x 64 B, hi+lo
            int idx = i * 256 + tid;
            int r = idx >> 2, c4 = idx & 3;
            long go = (long)r * DINN + kc + c4 * 8;
            uint32_t so = r * 80 + c4 * 16;
            cpa16(sb2 + G1_BH + so, g_WT_hi + go);
            cpa16(sb2 + G1_BL + so, g_WT_lo + go);
        }
        asm volatile("cp.async.commit_group;" ::: "memory");
    };

    const int arow = (((lane >> 3) & 1) * 8 + (lane & 7)) * 80;
    const int brow = (wid * 32 + ((lane >> 3) & 1) * 8 + (lane & 7)) * 80;

    auto COMPUTE = [&](int s) {
        const uint32_t base = sbase + s * G1_BUF;
        #pragma unroll
        for (int k16 = 0; k16 < 2; k16++) {
            const int kb = (k16 * 16 + (lane >> 4) * 8) * 2;
            uint32_t af[4][4];
            #pragma unroll
            for (int am = 0; am < 4; am++)
                LDSM_X4(af[am], base + G1_A + arow + am * 16 * 80 + kb);
            #pragma unroll
            for (int pr = 0; pr < 2; pr++) {
                uint32_t bh[4], bl[4];
                LDSM_X4(bh, base + G1_BH + brow + pr * 16 * 80 + kb);
                LDSM_X4(bl, base + G1_BL + brow + pr * 16 * 80 + kb);
                #pragma unroll
                for (int od = 0; od < 2; od++) {
                    const int an = pr * 2 + od;
                    #pragma unroll
                    for (int am = 0; am < 4; am++) {
                        MMA16816(acc[am][an], af[am], bh[od], bh[od + 2]);
                        MMA16816(acc[am][an], af[am], bl[od], bl[od + 2]);
                    }
                }
            }
        }
    };

    // 2-stage, single sync per iter; A staged in registers each iteration.
    const int nT = DINN / 32;     // 24
    ALOADR(0);
    ISSUE_B(0, 0);
    ASTORE(0);
    #pragma unroll 1
    for (int t = 0; t < nT; ++t) {
        if (t + 1 < nT) ALOADR((t + 1) * 32);
        asm volatile("cp.async.wait_group 0;" ::: "memory");
        __syncthreads();
        if (t + 1 < nT) {
            ISSUE_B((t + 1) * 32, (t + 1) & 1);
            ASTORE((t + 1) & 1);
        }
        COMPUTE(t & 1);
    }
    __syncthreads();

    // ---- epilogue ----
    float* st  = (float*)smem;                 // [256 dout][68] x fp32
    float* ps1 = (float*)(smem + 69632);       // [4][64]
    float* ps2 = (float*)(smem + 70656);
    int* pos_s = (int*)(smem + 2 * G1_BUF);    // 64 ints

    #pragma unroll
    for (int am = 0; am < 4; am++)
        #pragma unroll
        for (int an = 0; an < 4; an++) {
            const int r0 = am * 16 + (lane >> 2);
            const int c0 = wid * 32 + an * 8 + (lane & 3) * 2;
            st[c0 * STG1 + r0]           = acc[am][an][0];
            st[(c0 + 1) * STG1 + r0]     = acc[am][an][1];
            st[c0 * STG1 + r0 + 8]       = acc[am][an][2];
            st[(c0 + 1) * STG1 + r0 + 8] = acc[am][an][3];
        }
    if (tid < 64) pos_s[tid] = pos[b * NN + rowBase + tid];
    __syncthreads();

    // pass A: add pos-emb, write WhT fp16, update stage
    #pragma unroll 2
    for (int i = 0; i < 64; i++) {
        int idx = i * 256 + tid;
        int dl = idx >> 6, nl = idx & 63;
        float v = st[dl * STG1 + nl] + __ldg(pt + (long)pos_s[nl] * DOUTT + dl);
        st[dl * STG1 + nl] = v;
        g_WhT[((long)b * DOUTT + dl) * NN + rowBase + nl] = __float2half_rn(v);
    }
    __syncthreads();

    // pass B: fused s1/s2
    {
        const int node = tid & 63, q = tid >> 6;
        float v1 = 0.f, v2 = 0.f;
        #pragma unroll 4
        for (int c = 0; c < 64; c++) {
            int dl = q * 64 + c;
            float v = st[dl * STG1 + node];
            v1 += v * __ldg(a1v + dl);
            v2 += v * __ldg(a2v + dl);
        }
        ps1[q * 64 + node] = v1;
        ps2[q * 64 + node] = v2;
    }
    __syncthreads();
    if (tid < 64) {
        float s1 = ps1[tid] + ps1[64 + tid] + ps1[128 + tid] + ps1[192 + tid];
        float s2 = ps2[tid] + ps2[64 + tid] + ps2[128 + tid] + ps2[192 + tid];
        g_s1[b * NN + rowBase + tid] = s1;
        g_s2[b * NN + rowBase + tid] = s2;
    }
}

// ---------------------------------------------------------------------------
// GEMM2: hp[64 x 256] = att[64xK] * WhT, K=512, single fp16 product.
// 3-stage ring, one sync/iter. grid (8, BB); 8 warps of 64x32.
// ---------------------------------------------------------------------------
__global__ __launch_bounds__(256, 2)
void g2_gemm(float* __restrict__ hp)
{
    extern __shared__ char smem[];
    const uint32_t sbase = smem_u32(smem);
    const int tid = threadIdx.x, lane = tid & 31, wid = tid >> 5;
    const int b = blockIdx.y;
    const int rowBase = blockIdx.x * 64;

    float acc[4][4][4];
    #pragma unroll
    for (int i = 0; i < 4; i++)
        #pragma unroll
        for (int j = 0; j < 4; j++)
            #pragma unroll
            for (int r = 0; r < 4; r++) acc[i][j][r] = 0.f;

    auto ISSUE = [&](int kc, int s) {
        const uint32_t sb2 = sbase + s * G2_BUF;
        {   // A: att 64 rows x 64 B
            int r = tid >> 2, c4 = tid & 3;
            long go = ((long)b * NN + rowBase + r) * NN + kc + c4 * 8;
            cpa16(sb2 + G2_A + r * 80 + c4 * 16, g_att + go);
        }
        #pragma unroll
        for (int i = 0; i < 4; i++) {   // B: WhT 256 rows x 64 B
            int idx = i * 256 + tid;
            int r = idx >> 2, c4 = idx & 3;
            long go = ((long)b * DOUTT + r) * NN + kc + c4 * 8;
            cpa16(sb2 + G2_BH + r * 80 + c4 * 16, g_WhT + go);
        }
        asm volatile("cp.async.commit_group;" ::: "memory");
    };

    const int arow = (((lane >> 3) & 1) * 8 + (lane & 7)) * 80;
    const int brow = (wid * 32 + ((lane >> 3) & 1) * 8 + (lane & 7)) * 80;

    auto COMPUTE = [&](int s) {
        const uint32_t base = sbase + s * G2_BUF;
        #pragma unroll
        for (int k16 = 0; k16 < 2; k16++) {
            const int kb = (k16 * 16 + (lane >> 4) * 8) * 2;
            uint32_t af[4][4];
            #pragma unroll
            for (int am = 0; am < 4; am++)
                LDSM_X4(af[am], base + G2_A + arow + am * 16 * 80 + kb);
            #pragma unroll
            for (int pr = 0; pr < 2; pr++) {
                uint32_t bh[4];
                LDSM_X4(bh, base + G2_BH + brow + pr * 16 * 80 + kb);
                #pragma unroll
                for (int od = 0; od < 2; od++) {
                    const int an = pr * 2 + od;
                    #pragma unroll
                    for (int am = 0; am < 4; am++)
                        MMA16816(acc[am][an], af[am], bh[od], bh[od + 2]);
                }
            }
        }
    };

    const int nT = NN / 32;       // 16
    ISSUE(0, 0);
    ISSUE(32, 1);
    #pragma unroll 1
    for (int t = 0; t < nT; ++t) {
        if (t + 2 < nT) asm volatile("cp.async.wait_group 1;" ::: "memory");
        else            asm volatile("cp.async.wait_group 0;" ::: "memory");
        __syncthreads();
        if (t + 2 < nT) ISSUE((t + 2) * 32, (t + 2) % 3);
        COMPUTE(t % 3);
    }
    __syncthreads();

    // ---- epilogue: stage row-major, coalesced float4 out ----
    float* st = (float*)smem;
    #pragma unroll
    for (int am = 0; am < 4; am++)
        #pragma unroll
        for (int an = 0; an < 4; an++) {
            const int r0 = am * 16 + (lane >> 2);
            const int c0 = wid * 32 + an * 8 + (lane & 3) * 2;
            st[r0 * STG2 + c0]           = acc[am][an][0];
            st[r0 * STG2 + c0 + 1]       = acc[am][an][1];
            st[(r0 + 8) * STG2 + c0]     = acc[am][an][2];
            st[(r0 + 8) * STG2 + c0 + 1] = acc[am][an][3];
        }
    __syncthreads();
    #pragma unroll 4
    for (int i = 0; i < 16; i++) {
        int fid = i * 256 + tid;
        int r = fid >> 6, c4 = fid & 63;
        float4 v = *(const float4*)&st[r * STG2 + c4 * 4];
        *(float4*)&hp[((long)b * NN + rowBase + r) * DOUTT + c4 * 4] = v;
    }
}

// ---------------------------------------------------------------------------
// Masked-softmax attention row: fp32 att to d_out + fp16 scratch.
// ---------------------------------------------------------------------------
__global__ __launch_bounds__(128)
void k_attn(const int* __restrict__ adj, float* __restrict__ att)
{
    const int i = blockIdx.x, b = blockIdx.y;
    const long base = ((long)b * NN + i) * NN;
    const int t = threadIdx.x;
    const float s1v = g_s1[b * NN + i];

    const int4   a4 = *(const int4*)(adj + base + t * 4);
    const float4 s2 = *(const float4*)(g_s2 + b * NN + t * 4);

    float e[4];
    {
        float x;
        x = s1v + s2.x; x = x > 0.f ? x : SLOPE * x; e[0] = (a4.x > 0) ? x : NEGV;
        x = s1v + s2.y; x = x > 0.f ? x : SLOPE * x; e[1] = (a4.y > 0) ? x : NEGV;
        x = s1v + s2.z; x = x > 0.f ? x : SLOPE * x; e[2] = (a4.z > 0) ? x : NEGV;
        x = s1v + s2.w; x = x > 0.f ? x : SLOPE * x; e[3] = (a4.w > 0) ? x : NEGV;
    }

    __shared__ float red[4];
    float m = fmaxf(fmaxf(e[0], e[1]), fmaxf(e[2], e[3]));
    #pragma unroll
    for (int o = 16; o; o >>= 1) m = fmaxf(m, __shfl_xor_sync(0xffffffffu, m, o));
    if ((t & 31) == 0) red[t >> 5] = m;
    __syncthreads();
    float M = fmaxf(fmaxf(red[0], red[1]), fmaxf(red[2], red[3]));
    __syncthreads();

    float x0 = __expf(e[0] - M), x1 = __expf(e[1] - M);
    float x2 = __expf(e[2] - M), x3 = __expf(e[3] - M);
    float s = (x0 + x1) + (x2 + x3);
    #pragma unroll
    for (int o = 16; o; o >>= 1) s += __shfl_xor_sync(0xffffffffu, s, o);
    if ((t & 31) == 0) red[t >> 5] = s;
    __syncthreads();
    float inv = 1.f / (red[0] + red[1] + red[2] + red[3]);

    float v0 = x0 * inv, v1 = x1 * inv, v2 = x2 * inv, v3 = x3 * inv;
    *(float4*)(att + base + t * 4) = make_float4(v0, v1, v2, v3);
    *(uint2*)(g_att + base + t * 4) = make_uint2(pk2h(v0, v1), pk2h(v2, v3));
}

// ---------------------------------------------------------------------------
extern "C" void kernel_launch(void* const* d_in, const int* in_sizes, int n_in,
                              void* d_out, int out_size)
{
    const float* h   = (const float*)d_in[0];
    const int*   adj = (const int*)  d_in[1];
    const int*   pos = (const int*)  d_in[2];
    const float* W   = (const float*)d_in[3];
    const float* a1  = (const float*)d_in[4];
    const float* a2  = (const float*)d_in[5];
    const float* pt  = (const float*)d_in[6];

    float* out = (float*)d_out;
    float* hp  = out;                              // [B,N,DOUT]
    float* att = out + (long)BB * NN * DOUTT;      // [B,N,N]

    static int smem_set = 0;
    if (!smem_set) {
        cudaFuncSetAttribute(g1_gemm, cudaFuncAttributeMaxDynamicSharedMemorySize, G1_SMEM);
        cudaFuncSetAttribute(g2_gemm, cudaFuncAttributeMaxDynamicSharedMemorySize, G2_SMEM);
        smem_set = 1;
    }

    dim3 gT(DINN / 32, DOUTT / 32);                // (24, 8)
    k_transW<<<gT, 256>>>(W);

    dim3 gG(NN / 64, BB);                          // (8, 32) = 256 CTAs
    g1_gemm<<<gG, 256, G1_SMEM>>>(h, pos, pt, a1, a2);

    dim3 g3(NN, BB);                               // (512, 32)
    k_attn<<<g3, 128>>>(adj, att);

    g2_gemm<<<gG, 256, G2_SMEM>>>(hp);
}